// round 11
// baseline (speedup 1.0000x reference)
#include <cuda_runtime.h>
#include <cuda_fp16.h>
#include <cstdint>
#include <math_constants.h>

#define BB 8192
#define DD 256
#define TI 128
#define TJ 128
#define KC 64              // fp16 k-chunk = 128B rows
#define NCH (DD / KC)      // 4
#define NB  (BB / TI)      // 64
#define NTILES (NB * (NB + 1) / 2)   // 2080
#define GRID 296           // persistent: 148 SMs x 2 CTAs
#define MARGIN_F 0.3f

// dynamic smem layout: 2-stage
#define OFF_SQJ    0
#define OFF_LBLJ   512
#define OFF_SQI    1024
#define OFF_LBLI   1536
#define OFF_STAGE  2048
#define STAGE_BYTES 32768          // A tile 16KB + B tile 16KB
#define OFF_B      16384
#define SMEM_DYN   (OFF_STAGE + 2 * STAGE_BYTES)

__device__ __half g_xh[BB * DD];
__device__ float g_sq[BB];
__device__ unsigned int g_maxenc[BB];
__device__ unsigned int g_minenc[BB];
__device__ unsigned int g_done = 0;

__device__ __forceinline__ uint32_t smem_u32(const void* p) {
    uint32_t a;
    asm("{ .reg .u64 t; cvta.to.shared.u64 t, %1; cvt.u32.u64 %0, t; }" : "=r"(a) : "l"(p));
    return a;
}
__device__ __forceinline__ unsigned enc_f(float f) {
    unsigned u = __float_as_uint(f);
    return (u & 0x80000000u) ? ~u : (u | 0x80000000u);
}
__device__ __forceinline__ float dec_f(unsigned u) {
    return (u & 0x80000000u) ? __uint_as_float(u & 0x7FFFFFFFu) : __uint_as_float(~u);
}
#define CP_ASYNC(dst, src) \
    asm volatile("cp.async.cg.shared.global [%0], [%1], 16;" :: "r"(dst), "l"(src) : "memory")
#define CP_COMMIT() asm volatile("cp.async.commit_group;" ::: "memory")
#define CP_WAIT(n)  asm volatile("cp.async.wait_group " #n ";" ::: "memory")
#define LDSM4(r0,r1,r2,r3,a) \
    asm volatile("ldmatrix.sync.aligned.m8n8.x4.shared.b16 {%0,%1,%2,%3}, [%4];" \
                 : "=r"(r0),"=r"(r1),"=r"(r2),"=r"(r3) : "r"(a))
#define MMAH(d,a,b0,b1) \
    asm volatile("mma.sync.aligned.m16n8k16.row.col.f32.f16.f16.f32 " \
                 "{%0,%1,%2,%3}, {%4,%5,%6,%7}, {%8,%9}, {%0,%1,%2,%3};" \
                 : "+f"(d[0]),"+f"(d[1]),"+f"(d[2]),"+f"(d[3]) \
                 : "r"(a[0]),"r"(a[1]),"r"(a[2]),"r"(a[3]),"r"(b0),"r"(b1))

// ---------- 0) fp32 -> fp16, fused row norms + mining init (4 float4/thread) ----------
__global__ void prep_kernel(const float* __restrict__ x) {
    __shared__ float part[32];
    int tid = threadIdx.x, lane = tid & 31, wid = tid >> 5;
    float s[4];
    #pragma unroll
    for (int h = 0; h < 4; h++) {
        int i = blockIdx.x * 1024 + h * 256 + tid;     // float4 index; 16 rows/block
        float4 v = ((const float4*)x)[i];
        ((__half2*)g_xh)[2*i]   = __floats2half2_rn(v.x, v.y);
        ((__half2*)g_xh)[2*i+1] = __floats2half2_rn(v.z, v.w);
        s[h] = fmaf(v.x, v.x, fmaf(v.y, v.y, fmaf(v.z, v.z, v.w * v.w)));
    }
    #pragma unroll
    for (int h = 0; h < 4; h++) {
        float t = s[h];
        #pragma unroll
        for (int o = 16; o; o >>= 1) t += __shfl_down_sync(0xffffffffu, t, o);
        if (lane == 0) part[h * 8 + wid] = t;          // each warp covers half a row
    }
    __syncthreads();
    if (tid < 16) {
        int row = blockIdx.x * 16 + tid;
        g_sq[row] = part[tid * 2] + part[tid * 2 + 1];
        g_maxenc[row] = 0u;
        g_minenc[row] = 0xFFFFFFFFu;
    }
}

// decode upper-triangle tile index -> (bi, bj)
__device__ __forceinline__ void tile2ij(int tile, int& bi, int& bj) {
    int rem = tile; bi = 0;
    while (rem >= NB - bi) { rem -= NB - bi; bi++; }
    bj = bi + rem;
}

// ---------- 1) fp16 Gram tiles (persistent, 2-stage) + fused final reduce ----------
__global__ void __launch_bounds__(256, 2)
triplet_mma(const int* __restrict__ tgt, float* __restrict__ out) {
    extern __shared__ char smem[];
    __shared__ int s_win;
    const uint32_t sb = smem_u32(smem);
    const int tid = threadIdx.x, lane = tid & 31, wid = tid >> 5;
    const int wm = wid >> 2, wn = wid & 3;          // warp tile: rows wm*64, cols wn*32

    // loop-invariant fragment address components
    const int abit = lane >> 4;              // A chunk bit
    const int bbit = (lane >> 3) & 1;        // B chunk bit
    uint32_t browoff[2]; int bsw[2];
    #pragma unroll
    for (int p = 0; p < 2; p++) {
        int nrow = wn * 32 + p * 16 + (lane & 7) + ((lane >> 4) << 3);
        browoff[p] = (uint32_t)(nrow * 128);
        bsw[p] = nrow & 7;
    }
    uint32_t arowoff[4]; int asw[4];
    #pragma unroll
    for (int mt = 0; mt < 4; mt++) {
        int arow = wm * 64 + mt * 16 + (lane & 15);
        arowoff[mt] = (uint32_t)(arow * 128);
        asw[mt] = arow & 7;
    }

    auto issue_loads = [&](int i0, int j0, int c, int st) {
        const uint32_t abase = sb + OFF_STAGE + st * STAGE_BYTES;
        const uint32_t bbase = abase + OFF_B;
        const int kb = c * KC;
        #pragma unroll
        for (int t = 0; t < 4; t++) {
            int idx = t * 256 + tid;           // 0..1023
            int row = idx >> 3;                // 0..127
            int ch  = idx & 7;
            uint32_t d = (uint32_t)((ch ^ (row & 7)) * 16);
            const __half* sA = g_xh + (size_t)(i0 + row) * DD + kb + ch * 8;
            const __half* sB = g_xh + (size_t)(j0 + row) * DD + kb + ch * 8;
            CP_ASYNC(abase + row * 128 + d, sA);
            CP_ASYNC(bbase + row * 128 + d, sB);
        }
        CP_COMMIT();
    };

    int bi, bj;
    tile2ij(blockIdx.x, bi, bj);
    if (blockIdx.x < NTILES) issue_loads(bi * TI, bj * TJ, 0, 0);   // prologue prefetch

    for (int tile = blockIdx.x; tile < NTILES; tile += GRID) {
        const int i0 = bi * TI, j0 = bj * TJ;
        const bool diag = (bi == bj);
        int nbi = 0, nbj = 0;
        const bool has_next = (tile + GRID < NTILES);
        if (has_next) tile2ij(tile + GRID, nbi, nbj);

        __syncthreads();   // prev epilogue done before sq/lbl smem rewrite
        if (tid < TJ) {
            ((float*)(smem + OFF_SQJ))[tid] = g_sq[j0 + tid];
            ((int*)(smem + OFF_LBLJ))[tid]  = tgt[j0 + tid];
        } else {
            int r = tid - TJ;
            ((float*)(smem + OFF_SQI))[r] = g_sq[i0 + r];
            ((int*)(smem + OFF_LBLI))[r]  = tgt[i0 + r];
        }

        float acc[4][4][4];
        #pragma unroll
        for (int mt = 0; mt < 4; mt++)
            #pragma unroll
            for (int nt = 0; nt < 4; nt++)
                #pragma unroll
                for (int e = 0; e < 4; e++) acc[mt][nt][e] = 0.f;

        for (int c = 0; c < NCH; c++) {
            bool issued = true;
            if (c + 1 < NCH)   issue_loads(i0, j0, c + 1, (c + 1) & 1);
            else if (has_next) issue_loads(nbi * TI, nbj * TJ, 0, 0);   // cross-tile prefetch
            else               issued = false;
            if (issued) { CP_WAIT(1); } else { CP_WAIT(0); }   // current chunk landed
            __syncthreads();

            const uint32_t abase = sb + OFF_STAGE + (c & 1) * STAGE_BYTES;
            const uint32_t bbase = abase + OFF_B;

            #pragma unroll
            for (int ks = 0; ks < 4; ks++) {      // 4 k16 steps per 64-chunk
                uint32_t bh[8];
                #pragma unroll
                for (int p = 0; p < 2; p++) {
                    int ch = ks * 2 + bbit;
                    uint32_t a_ = bbase + browoff[p] + (uint32_t)((ch ^ bsw[p]) << 4);
                    LDSM4(bh[p*4+0], bh[p*4+1], bh[p*4+2], bh[p*4+3], a_);
                }
                #pragma unroll
                for (int mt = 0; mt < 4; mt++) {
                    int ch = ks * 2 + abit;
                    uint32_t a_ = abase + arowoff[mt] + (uint32_t)((ch ^ asw[mt]) << 4);
                    uint32_t ar[4];
                    LDSM4(ar[0], ar[1], ar[2], ar[3], a_);
                    #pragma unroll
                    for (int nt = 0; nt < 4; nt++) {
                        uint32_t b0 = bh[(nt >> 1) * 4 + (nt & 1) * 2];
                        uint32_t b1 = bh[(nt >> 1) * 4 + (nt & 1) * 2 + 1];
                        MMAH(acc[mt][nt], ar, b0, b1);
                    }
                }
            }
            if (c + 1 < NCH) __syncthreads();   // stage reuse guard
        }

        const float* sSqJ  = (const float*)(smem + OFF_SQJ);
        const int*   sLblJ = (const int*)(smem + OFF_LBLJ);
        const float* sSqI  = (const float*)(smem + OFF_SQI);
        const int*   sLblI = (const int*)(smem + OFF_LBLI);

        // ---- row-side mining: val = sq[j] - 2*dot (sq[i] cancels downstream) ----
        #pragma unroll
        for (int mt = 0; mt < 4; mt++) {
            #pragma unroll
            for (int half = 0; half < 2; half++) {
                int li    = wm * 64 + mt * 16 + (lane >> 2) + half * 8;
                int mylbl = sLblI[li];
                float mp = -CUDART_INF_F, mn = CUDART_INF_F;
                #pragma unroll
                for (int nt = 0; nt < 4; nt++) {
                    int jl = wn * 32 + nt * 8 + (lane & 3) * 2;
                    float v0 = fmaf(-2.f, acc[mt][nt][half * 2],     sSqJ[jl]);
                    float v1 = fmaf(-2.f, acc[mt][nt][half * 2 + 1], sSqJ[jl + 1]);
                    if (sLblJ[jl]     == mylbl) mp = fmaxf(mp, v0); else mn = fminf(mn, v0);
                    if (sLblJ[jl + 1] == mylbl) mp = fmaxf(mp, v1); else mn = fminf(mn, v1);
                }
                #pragma unroll
                for (int o = 1; o <= 2; o <<= 1) {
                    mp = fmaxf(mp, __shfl_xor_sync(0xffffffffu, mp, o));
                    mn = fminf(mn, __shfl_xor_sync(0xffffffffu, mn, o));
                }
                if ((lane & 3) == 0) {
                    atomicMax(&g_maxenc[i0 + li], enc_f(mp));
                    atomicMin(&g_minenc[i0 + li], enc_f(mn));
                }
            }
        }
        // ---- col-side mining (off-diag only): val = sq[i] - 2*dot ----
        if (!diag) {
            #pragma unroll
            for (int nt = 0; nt < 4; nt++) {
                #pragma unroll
                for (int e = 0; e < 2; e++) {
                    int lj    = wn * 32 + nt * 8 + (lane & 3) * 2 + e;
                    int jlbl  = sLblJ[lj];
                    float mp = -CUDART_INF_F, mn = CUDART_INF_F;
                    #pragma unroll
                    for (int mt = 0; mt < 4; mt++) {
                        #pragma unroll
                        for (int half = 0; half < 2; half++) {
                            int li = wm * 64 + mt * 16 + (lane >> 2) + half * 8;
                            float v = fmaf(-2.f, acc[mt][nt][half * 2 + e], sSqI[li]);
                            if (sLblI[li] == jlbl) mp = fmaxf(mp, v);
                            else                   mn = fminf(mn, v);
                        }
                    }
                    #pragma unroll
                    for (int o = 4; o <= 16; o <<= 1) {
                        mp = fmaxf(mp, __shfl_xor_sync(0xffffffffu, mp, o));
                        mn = fminf(mn, __shfl_xor_sync(0xffffffffu, mn, o));
                    }
                    if (lane < 4) {
                        atomicMax(&g_maxenc[j0 + lj], enc_f(mp));
                        atomicMin(&g_minenc[j0 + lj], enc_f(mn));
                    }
                }
            }
        }

        bi = nbi; bj = nbj;
    }

    // ---- fused final reduce: last CTA to finish computes loss & precision ----
    __syncthreads();
    if (tid == 0) {
        __threadfence();
        unsigned old = atomicAdd(&g_done, 1u);
        s_win = (old == GRID - 1) ? 1 : 0;
    }
    __syncthreads();
    if (s_win) {
        __threadfence();
        __shared__ float wl[8], wp[8];
        float lsum = 0.f, pcnt = 0.f;
        for (int i = tid; i < BB; i += 256) {
            float mp = dec_f(__ldcg(&g_maxenc[i]));
            float mn = dec_f(__ldcg(&g_minenc[i]));
            float d = mp - mn + MARGIN_F;        // == dist_ap - dist_an + margin
            lsum += (d > 0.f) ? d : 0.f;
            pcnt += (mn > mp) ? 1.f : 0.f;
        }
        #pragma unroll
        for (int o = 16; o; o >>= 1) {
            lsum += __shfl_down_sync(0xffffffffu, lsum, o);
            pcnt += __shfl_down_sync(0xffffffffu, pcnt, o);
        }
        if (lane == 0) { wl[wid] = lsum; wp[wid] = pcnt; }
        __syncthreads();
        if (wid == 0 && lane < 8) {
            float l = wl[lane], p = wp[lane];
            #pragma unroll
            for (int o = 4; o; o >>= 1) {
                l += __shfl_down_sync(0x000000ffu, l, o);
                p += __shfl_down_sync(0x000000ffu, p, o);
            }
            if (lane == 0) {
                out[0] = l / (float)BB;
                out[1] = p / (float)BB;
                g_done = 0;                      // reset for next graph replay
            }
        }
    }
}

extern "C" void kernel_launch(void* const* d_in, const int* in_sizes, int n_in,
                              void* d_out, int out_size) {
    const float* x = (const float*)d_in[0];
    const int*   t = (const int*)d_in[1];   // JAX x64-disabled: int32
    float*       o = (float*)d_out;

    cudaFuncSetAttribute(triplet_mma, cudaFuncAttributeMaxDynamicSharedMemorySize, SMEM_DYN);

    prep_kernel<<<BB * DD / 4 / 1024, 256>>>(x);
    triplet_mma<<<GRID, 256, SMEM_DYN>>>(t, o);
}

// round 12
// speedup vs baseline: 1.2618x; 1.2618x over previous
#include <cuda_runtime.h>
#include <cuda_fp16.h>
#include <cstdint>
#include <math_constants.h>

#define BB 8192
#define DD 256
#define TI 128
#define TJ 128
#define KC 64              // fp16 k-chunk = 128B rows
#define NCH (DD / KC)      // 4
#define NB  (BB / TI)      // 64
#define NTILES (NB * (NB + 1) / 2)   // 2080
#define GRID 296           // persistent: 148 SMs x 2 CTAs
#define MARGIN_F 0.3f

// dynamic smem layout: 2-stage
#define OFF_SQJ    0
#define OFF_LBLJ   512
#define OFF_SQI    1024
#define OFF_LBLI   1536
#define OFF_STAGE  2048
#define STAGE_BYTES 32768          // A tile 16KB + B tile 16KB
#define OFF_B      16384
#define SMEM_DYN   (OFF_STAGE + 2 * STAGE_BYTES)

__device__ __half g_xh[BB * DD];
__device__ float g_sq[BB];
__device__ unsigned int g_maxenc[BB];
__device__ unsigned int g_minenc[BB];

__device__ __forceinline__ uint32_t smem_u32(const void* p) {
    uint32_t a;
    asm("{ .reg .u64 t; cvta.to.shared.u64 t, %1; cvt.u32.u64 %0, t; }" : "=r"(a) : "l"(p));
    return a;
}
__device__ __forceinline__ unsigned enc_f(float f) {
    unsigned u = __float_as_uint(f);
    return (u & 0x80000000u) ? ~u : (u | 0x80000000u);
}
__device__ __forceinline__ float dec_f(unsigned u) {
    return (u & 0x80000000u) ? __uint_as_float(u & 0x7FFFFFFFu) : __uint_as_float(~u);
}
#define CP_ASYNC(dst, src) \
    asm volatile("cp.async.cg.shared.global [%0], [%1], 16;" :: "r"(dst), "l"(src) : "memory")
#define CP_COMMIT() asm volatile("cp.async.commit_group;" ::: "memory")
#define CP_WAIT(n)  asm volatile("cp.async.wait_group " #n ";" ::: "memory")
#define LDSM4(r0,r1,r2,r3,a) \
    asm volatile("ldmatrix.sync.aligned.m8n8.x4.shared.b16 {%0,%1,%2,%3}, [%4];" \
                 : "=r"(r0),"=r"(r1),"=r"(r2),"=r"(r3) : "r"(a))
#define MMAH(d,a,b0,b1) \
    asm volatile("mma.sync.aligned.m16n8k16.row.col.f32.f16.f16.f32 " \
                 "{%0,%1,%2,%3}, {%4,%5,%6,%7}, {%8,%9}, {%0,%1,%2,%3};" \
                 : "+f"(d[0]),"+f"(d[1]),"+f"(d[2]),"+f"(d[3]) \
                 : "r"(a[0]),"r"(a[1]),"r"(a[2]),"r"(a[3]),"r"(b0),"r"(b1))

// ---------- 0) fp32 -> fp16, fused row norms + mining init (4 float4/thread) ----------
__global__ void prep_kernel(const float* __restrict__ x) {
    __shared__ float part[32];
    int tid = threadIdx.x, lane = tid & 31, wid = tid >> 5;
    float s[4];
    #pragma unroll
    for (int h = 0; h < 4; h++) {
        int i = blockIdx.x * 1024 + h * 256 + tid;     // float4 index; 16 rows/block
        float4 v = ((const float4*)x)[i];
        ((__half2*)g_xh)[2*i]   = __floats2half2_rn(v.x, v.y);
        ((__half2*)g_xh)[2*i+1] = __floats2half2_rn(v.z, v.w);
        s[h] = fmaf(v.x, v.x, fmaf(v.y, v.y, fmaf(v.z, v.z, v.w * v.w)));
    }
    #pragma unroll
    for (int h = 0; h < 4; h++) {
        float t = s[h];
        #pragma unroll
        for (int o = 16; o; o >>= 1) t += __shfl_down_sync(0xffffffffu, t, o);
        if (lane == 0) part[h * 8 + wid] = t;          // each warp covers half a row
    }
    __syncthreads();
    if (tid < 16) {
        int row = blockIdx.x * 16 + tid;
        g_sq[row] = part[tid * 2] + part[tid * 2 + 1];
        g_maxenc[row] = 0u;
        g_minenc[row] = 0xFFFFFFFFu;
    }
}

// decode upper-triangle tile index -> (bi, bj)
__device__ __forceinline__ void tile2ij(int tile, int& bi, int& bj) {
    int rem = tile; bi = 0;
    while (rem >= NB - bi) { rem -= NB - bi; bi++; }
    bj = bi + rem;
}

// ---------- 1) fp16 Gram tiles (upper triangle, persistent, prefetch-overlap) ----------
// Tiles: 128 rows x 128B (8 chunks), swizzle ch ^ (row & 7) -> conflict-free ldmatrix.
__global__ void __launch_bounds__(256, 2)
triplet_mma(const int* __restrict__ tgt) {
    extern __shared__ char smem[];
    const uint32_t sb = smem_u32(smem);
    const int tid = threadIdx.x, lane = tid & 31, wid = tid >> 5;
    const int wm = wid >> 2, wn = wid & 3;          // warp tile: rows wm*64, cols wn*32

    auto issue_loads = [&](int i0, int j0, int c, int st) {
        const uint32_t abase = sb + OFF_STAGE + st * STAGE_BYTES;
        const uint32_t bbase = abase + OFF_B;
        const int kb = c * KC;
        #pragma unroll
        for (int t = 0; t < 4; t++) {
            int idx = t * 256 + tid;           // 0..1023
            int row = idx >> 3;                // 0..127
            int ch  = idx & 7;
            uint32_t d = (uint32_t)((ch ^ (row & 7)) * 16);
            const __half* sA = g_xh + (size_t)(i0 + row) * DD + kb + ch * 8;
            const __half* sB = g_xh + (size_t)(j0 + row) * DD + kb + ch * 8;
            CP_ASYNC(abase + row * 128 + d, sA);
            CP_ASYNC(bbase + row * 128 + d, sB);
        }
        CP_COMMIT();
    };

    int bi, bj;
    tile2ij(blockIdx.x, bi, bj);
    if (blockIdx.x < NTILES) issue_loads(bi * TI, bj * TJ, 0, 0);   // prologue prefetch

    for (int tile = blockIdx.x; tile < NTILES; tile += GRID) {
        const int i0 = bi * TI, j0 = bj * TJ;
        const bool diag = (bi == bj);
        int nbi = 0, nbj = 0;
        const bool has_next = (tile + GRID < NTILES);
        if (has_next) tile2ij(tile + GRID, nbi, nbj);

        __syncthreads();   // prev epilogue done before sq/lbl smem rewrite
        if (tid < TJ) {
            ((float*)(smem + OFF_SQJ))[tid] = g_sq[j0 + tid];
            ((int*)(smem + OFF_LBLJ))[tid]  = tgt[j0 + tid];
        } else {
            int r = tid - TJ;
            ((float*)(smem + OFF_SQI))[r] = g_sq[i0 + r];
            ((int*)(smem + OFF_LBLI))[r]  = tgt[i0 + r];
        }

        float acc[4][4][4];
        #pragma unroll
        for (int mt = 0; mt < 4; mt++)
            #pragma unroll
            for (int nt = 0; nt < 4; nt++)
                #pragma unroll
                for (int e = 0; e < 4; e++) acc[mt][nt][e] = 0.f;

        for (int c = 0; c < NCH; c++) {
            if (c + 1 < NCH) {
                issue_loads(i0, j0, c + 1, (c + 1) & 1);
                CP_WAIT(1);
            } else if (has_next) {
                issue_loads(nbi * TI, nbj * TJ, 0, 0);   // cross-tile prefetch
                CP_WAIT(1);
            } else {
                CP_WAIT(0);                               // nothing new: drain fully
            }
            __syncthreads();

            const uint32_t abase = sb + OFF_STAGE + (c & 1) * STAGE_BYTES;
            const uint32_t bbase = abase + OFF_B;

            #pragma unroll
            for (int ks = 0; ks < 4; ks++) {      // 4 k16 steps per 64-chunk
                uint32_t bh[8];
                #pragma unroll
                for (int p = 0; p < 2; p++) {
                    int nrow = wn * 32 + p * 16 + (lane & 7) + ((lane >> 4) << 3);
                    int ch   = ks * 2 + ((lane >> 3) & 1);
                    uint32_t a_ = bbase + nrow * 128 + (uint32_t)((ch ^ (nrow & 7)) * 16);
                    LDSM4(bh[p*4+0], bh[p*4+1], bh[p*4+2], bh[p*4+3], a_);
                }
                #pragma unroll
                for (int mt = 0; mt < 4; mt++) {
                    int arow = wm * 64 + mt * 16 + (lane & 15);
                    int ch   = ks * 2 + (lane >> 4);
                    uint32_t a_ = abase + arow * 128 + (uint32_t)((ch ^ (arow & 7)) * 16);
                    uint32_t ar[4];
                    LDSM4(ar[0], ar[1], ar[2], ar[3], a_);
                    #pragma unroll
                    for (int nt = 0; nt < 4; nt++) {
                        uint32_t b0 = bh[(nt >> 1) * 4 + (nt & 1) * 2];
                        uint32_t b1 = bh[(nt >> 1) * 4 + (nt & 1) * 2 + 1];
                        MMAH(acc[mt][nt], ar, b0, b1);
                    }
                }
            }
            if (c + 1 < NCH) __syncthreads();   // stage reuse guard
        }

        const float* sSqJ  = (const float*)(smem + OFF_SQJ);
        const int*   sLblJ = (const int*)(smem + OFF_LBLJ);
        const float* sSqI  = (const float*)(smem + OFF_SQI);
        const int*   sLblI = (const int*)(smem + OFF_LBLI);

        // ---- row-side mining: val = sq[j] - 2*dot (sq[i] cancels downstream) ----
        #pragma unroll
        for (int mt = 0; mt < 4; mt++) {
            #pragma unroll
            for (int half = 0; half < 2; half++) {
                int li    = wm * 64 + mt * 16 + (lane >> 2) + half * 8;
                int mylbl = sLblI[li];
                float mp = -CUDART_INF_F, mn = CUDART_INF_F;
                #pragma unroll
                for (int nt = 0; nt < 4; nt++) {
                    int jl = wn * 32 + nt * 8 + (lane & 3) * 2;
                    float v0 = fmaf(-2.f, acc[mt][nt][half * 2],     sSqJ[jl]);
                    float v1 = fmaf(-2.f, acc[mt][nt][half * 2 + 1], sSqJ[jl + 1]);
                    if (sLblJ[jl]     == mylbl) mp = fmaxf(mp, v0); else mn = fminf(mn, v0);
                    if (sLblJ[jl + 1] == mylbl) mp = fmaxf(mp, v1); else mn = fminf(mn, v1);
                }
                #pragma unroll
                for (int o = 1; o <= 2; o <<= 1) {
                    mp = fmaxf(mp, __shfl_xor_sync(0xffffffffu, mp, o));
                    mn = fminf(mn, __shfl_xor_sync(0xffffffffu, mn, o));
                }
                if ((lane & 3) == 0) {
                    atomicMax(&g_maxenc[i0 + li], enc_f(mp));
                    atomicMin(&g_minenc[i0 + li], enc_f(mn));
                }
            }
        }
        // ---- col-side mining (off-diag only): val = sq[i] - 2*dot ----
        if (!diag) {
            #pragma unroll
            for (int nt = 0; nt < 4; nt++) {
                #pragma unroll
                for (int e = 0; e < 2; e++) {
                    int lj    = wn * 32 + nt * 8 + (lane & 3) * 2 + e;
                    int jlbl  = sLblJ[lj];
                    float mp = -CUDART_INF_F, mn = CUDART_INF_F;
                    #pragma unroll
                    for (int mt = 0; mt < 4; mt++) {
                        #pragma unroll
                        for (int half = 0; half < 2; half++) {
                            int li = wm * 64 + mt * 16 + (lane >> 2) + half * 8;
                            float v = fmaf(-2.f, acc[mt][nt][half * 2 + e], sSqI[li]);
                            if (sLblI[li] == jlbl) mp = fmaxf(mp, v);
                            else                   mn = fminf(mn, v);
                        }
                    }
                    #pragma unroll
                    for (int o = 4; o <= 16; o <<= 1) {
                        mp = fmaxf(mp, __shfl_xor_sync(0xffffffffu, mp, o));
                        mn = fminf(mn, __shfl_xor_sync(0xffffffffu, mn, o));
                    }
                    if (lane < 4) {
                        atomicMax(&g_maxenc[j0 + lj], enc_f(mp));
                        atomicMin(&g_minenc[j0 + lj], enc_f(mn));
                    }
                }
            }
        }

        bi = nbi; bj = nbj;
    }
}

// ---------- 2) final: decode, loss & precision (shuffle tree) ----------
__global__ void triplet_final(float* __restrict__ out) {
    __shared__ float wl[32], wp[32];
    int tid = threadIdx.x, lane = tid & 31, wid = tid >> 5;
    float lsum = 0.f, pcnt = 0.f;
    for (int i = tid; i < BB; i += 1024) {
        float mp = dec_f(g_maxenc[i]);
        float mn = dec_f(g_minenc[i]);
        float d = mp - mn + MARGIN_F;        // == dist_ap - dist_an + margin
        lsum += (d > 0.f) ? d : 0.f;
        pcnt += (mn > mp) ? 1.f : 0.f;
    }
    #pragma unroll
    for (int o = 16; o; o >>= 1) {
        lsum += __shfl_down_sync(0xffffffffu, lsum, o);
        pcnt += __shfl_down_sync(0xffffffffu, pcnt, o);
    }
    if (lane == 0) { wl[wid] = lsum; wp[wid] = pcnt; }
    __syncthreads();
    if (wid == 0) {
        float l = wl[lane], p = wp[lane];
        #pragma unroll
        for (int o = 16; o; o >>= 1) {
            l += __shfl_down_sync(0xffffffffu, l, o);
            p += __shfl_down_sync(0xffffffffu, p, o);
        }
        if (lane == 0) {
            out[0] = l / (float)BB;
            out[1] = p / (float)BB;
        }
    }
}

extern "C" void kernel_launch(void* const* d_in, const int* in_sizes, int n_in,
                              void* d_out, int out_size) {
    const float* x = (const float*)d_in[0];
    const int*   t = (const int*)d_in[1];   // JAX x64-disabled: int32
    float*       o = (float*)d_out;

    cudaFuncSetAttribute(triplet_mma, cudaFuncAttributeMaxDynamicSharedMemorySize, SMEM_DYN);

    prep_kernel<<<BB * DD / 4 / 1024, 256>>>(x);
    triplet_mma<<<GRID, 256, SMEM_DYN>>>(t);
    triplet_final<<<1, 1024>>>(o);
}

// round 13
// speedup vs baseline: 1.3177x; 1.0443x over previous
#include <cuda_runtime.h>
#include <cuda_fp16.h>
#include <cstdint>
#include <math_constants.h>

#define BB 8192
#define DD 256
#define TI 128
#define TJ 128
#define KC 64              // fp16 k-chunk = 128B rows
#define NCH (DD / KC)      // 4
#define NB  (BB / TI)      // 64
#define NTILES (NB * (NB + 1) / 2)   // 2080
#define GRID 296           // persistent: 148 SMs x 2 CTAs
#define MARGIN_F 0.3f

// dynamic smem layout: 2-stage
#define OFF_SQJ    0
#define OFF_LBLJ   512
#define OFF_SQI    1024
#define OFF_LBLI   1536
#define OFF_STAGE  2048
#define STAGE_BYTES 32768          // A tile 16KB + B tile 16KB
#define OFF_B      16384
#define SMEM_DYN   (OFF_STAGE + 2 * STAGE_BYTES)

__device__ __half g_xh[BB * DD];
__device__ float g_sq[BB];
__device__ unsigned int g_maxenc[BB];
__device__ unsigned int g_minenc[BB];

__device__ __forceinline__ uint32_t smem_u32(const void* p) {
    uint32_t a;
    asm("{ .reg .u64 t; cvta.to.shared.u64 t, %1; cvt.u32.u64 %0, t; }" : "=r"(a) : "l"(p));
    return a;
}
__device__ __forceinline__ unsigned enc_f(float f) {
    unsigned u = __float_as_uint(f);
    return (u & 0x80000000u) ? ~u : (u | 0x80000000u);
}
__device__ __forceinline__ float dec_f(unsigned u) {
    return (u & 0x80000000u) ? __uint_as_float(u & 0x7FFFFFFFu) : __uint_as_float(~u);
}
#define CP_ASYNC(dst, src) \
    asm volatile("cp.async.cg.shared.global [%0], [%1], 16;" :: "r"(dst), "l"(src) : "memory")
#define CP_COMMIT() asm volatile("cp.async.commit_group;" ::: "memory")
#define CP_WAIT(n)  asm volatile("cp.async.wait_group " #n ";" ::: "memory")
#define LDSM4(r0,r1,r2,r3,a) \
    asm volatile("ldmatrix.sync.aligned.m8n8.x4.shared.b16 {%0,%1,%2,%3}, [%4];" \
                 : "=r"(r0),"=r"(r1),"=r"(r2),"=r"(r3) : "r"(a))
#define MMAH(d,a,b0,b1) \
    asm volatile("mma.sync.aligned.m16n8k16.row.col.f32.f16.f16.f32 " \
                 "{%0,%1,%2,%3}, {%4,%5,%6,%7}, {%8,%9}, {%0,%1,%2,%3};" \
                 : "+f"(d[0]),"+f"(d[1]),"+f"(d[2]),"+f"(d[3]) \
                 : "r"(a[0]),"r"(a[1]),"r"(a[2]),"r"(a[3]),"r"(b0),"r"(b1))

// ---------- 0) fp32 -> fp16 + row norms + mining init (warp-per-row, no smem) ----------
__global__ void prep_kernel(const float* __restrict__ x) {
    int lane = threadIdx.x & 31, wrp = threadIdx.x >> 5;
    int row  = blockIdx.x * 8 + wrp;
    const float4* src = (const float4*)(x + (size_t)row * DD);
    uint4* dst = (uint4*)(g_xh + (size_t)row * DD);
    float s = 0.f;
    #pragma unroll
    for (int h = 0; h < 2; h++) {
        float4 v0 = src[lane * 2 + h * 64];          // contiguous 32-lane sweep? no:
        // lane*2+h gives lane-contig pairs; use [lane + h*32] pattern instead for coalescing
        (void)v0;
        break;
    }
    // coalesced: each lane handles float4 indices {lane, lane+32}; store uint4 per pair is
    // not contiguous, so store two half2-pairs (8B) per float4 instead.
    #pragma unroll
    for (int h = 0; h < 2; h++) {
        int idx = lane + h * 32;                     // 0..63 within row
        float4 v = src[idx];
        __half2 p0 = __floats2half2_rn(v.x, v.y);
        __half2 p1 = __floats2half2_rn(v.z, v.w);
        ((__half2*)dst)[idx * 2]     = p0;
        ((__half2*)dst)[idx * 2 + 1] = p1;
        s = fmaf(v.x, v.x, fmaf(v.y, v.y, fmaf(v.z, v.z, fmaf(v.w, v.w, s))));
    }
    #pragma unroll
    for (int o = 16; o; o >>= 1) s += __shfl_down_sync(0xffffffffu, s, o);
    if (lane == 0) {
        g_sq[row] = s;
        g_maxenc[row] = 0u;
        g_minenc[row] = 0xFFFFFFFFu;
    }
}

// decode upper-triangle tile index -> (bi, bj)
__device__ __forceinline__ void tile2ij(int tile, int& bi, int& bj) {
    int rem = tile; bi = 0;
    while (rem >= NB - bi) { rem -= NB - bi; bi++; }
    bj = bi + rem;
}

// ---------- 1) fp16 Gram tiles (upper triangle, persistent, prefetch-overlap) ----------
// Tiles: 128 rows x 128B (8 chunks), swizzle ch ^ (row & 7) -> conflict-free ldmatrix.
__global__ void __launch_bounds__(256, 2)
triplet_mma(const int* __restrict__ tgt) {
    extern __shared__ char smem[];
    const uint32_t sb = smem_u32(smem);
    const int tid = threadIdx.x, lane = tid & 31, wid = tid >> 5;
    const int wm = wid >> 2, wn = wid & 3;          // warp tile: rows wm*64, cols wn*32

    auto issue_loads = [&](int i0, int j0, int c, int st) {
        const uint32_t abase = sb + OFF_STAGE + st * STAGE_BYTES;
        const uint32_t bbase = abase + OFF_B;
        const int kb = c * KC;
        #pragma unroll
        for (int t = 0; t < 4; t++) {
            int idx = t * 256 + tid;           // 0..1023
            int row = idx >> 3;                // 0..127
            int ch  = idx & 7;
            uint32_t d = (uint32_t)((ch ^ (row & 7)) * 16);
            const __half* sA = g_xh + (size_t)(i0 + row) * DD + kb + ch * 8;
            const __half* sB = g_xh + (size_t)(j0 + row) * DD + kb + ch * 8;
            CP_ASYNC(abase + row * 128 + d, sA);
            CP_ASYNC(bbase + row * 128 + d, sB);
        }
        CP_COMMIT();
    };

    auto compute_chunk = [&](uint32_t abase, uint32_t bbase, float (*acc)[4][4]) {
        #pragma unroll
        for (int ks = 0; ks < 4; ks++) {      // 4 k16 steps per 64-chunk
            uint32_t bh[8];
            #pragma unroll
            for (int p = 0; p < 2; p++) {
                int nrow = wn * 32 + p * 16 + (lane & 7) + ((lane >> 4) << 3);
                int ch   = ks * 2 + ((lane >> 3) & 1);
                uint32_t a_ = bbase + nrow * 128 + (uint32_t)((ch ^ (nrow & 7)) * 16);
                LDSM4(bh[p*4+0], bh[p*4+1], bh[p*4+2], bh[p*4+3], a_);
            }
            #pragma unroll
            for (int mt = 0; mt < 4; mt++) {
                int arow = wm * 64 + mt * 16 + (lane & 15);
                int ch   = ks * 2 + (lane >> 4);
                uint32_t a_ = abase + arow * 128 + (uint32_t)((ch ^ (arow & 7)) * 16);
                uint32_t ar[4];
                LDSM4(ar[0], ar[1], ar[2], ar[3], a_);
                #pragma unroll
                for (int nt = 0; nt < 4; nt++) {
                    uint32_t b0 = bh[(nt >> 1) * 4 + (nt & 1) * 2];
                    uint32_t b1 = bh[(nt >> 1) * 4 + (nt & 1) * 2 + 1];
                    MMAH(acc[mt][nt], ar, b0, b1);
                }
            }
        }
    };

    int bi, bj;
    tile2ij(blockIdx.x, bi, bj);
    if (blockIdx.x < NTILES) issue_loads(bi * TI, bj * TJ, 0, 0);   // prologue prefetch

    for (int tile = blockIdx.x; tile < NTILES; tile += GRID) {
        const int i0 = bi * TI, j0 = bj * TJ;
        const bool diag = (bi == bj);
        int nbi = 0, nbj = 0;
        const bool has_next = (tile + GRID < NTILES);
        if (has_next) tile2ij(tile + GRID, nbi, nbj);

        __syncthreads();   // prev epilogue done before sq/lbl smem rewrite
        if (tid < TJ) {
            ((float*)(smem + OFF_SQJ))[tid] = g_sq[j0 + tid];
            ((int*)(smem + OFF_LBLJ))[tid]  = tgt[j0 + tid];
        } else {
            int r = tid - TJ;
            ((float*)(smem + OFF_SQI))[r] = g_sq[i0 + r];
            ((int*)(smem + OFF_LBLI))[r]  = tgt[i0 + r];
        }

        float acc[4][4][4];
        #pragma unroll
        for (int mt = 0; mt < 4; mt++)
            #pragma unroll
            for (int nt = 0; nt < 4; nt++)
                #pragma unroll
                for (int e = 0; e < 4; e++) acc[mt][nt][e] = 0.f;

        // fully-unrolled chunk sequence: static stages, static branches
        // c = 0
        issue_loads(i0, j0, 1, 1); CP_WAIT(1); __syncthreads();
        compute_chunk(sb + OFF_STAGE, sb + OFF_STAGE + OFF_B, acc);
        __syncthreads();
        // c = 1
        issue_loads(i0, j0, 2, 0); CP_WAIT(1); __syncthreads();
        compute_chunk(sb + OFF_STAGE + STAGE_BYTES, sb + OFF_STAGE + STAGE_BYTES + OFF_B, acc);
        __syncthreads();
        // c = 2
        issue_loads(i0, j0, 3, 1); CP_WAIT(1); __syncthreads();
        compute_chunk(sb + OFF_STAGE, sb + OFF_STAGE + OFF_B, acc);
        __syncthreads();
        // c = 3
        if (has_next) { issue_loads(nbi * TI, nbj * TJ, 0, 0); CP_WAIT(1); }
        else          { CP_WAIT(0); }
        __syncthreads();
        compute_chunk(sb + OFF_STAGE + STAGE_BYTES, sb + OFF_STAGE + STAGE_BYTES + OFF_B, acc);

        const float* sSqJ  = (const float*)(smem + OFF_SQJ);
        const int*   sLblJ = (const int*)(smem + OFF_LBLJ);
        const float* sSqI  = (const float*)(smem + OFF_SQI);
        const int*   sLblI = (const int*)(smem + OFF_LBLI);

        // ---- row-side mining: val = sq[j] - 2*dot (sq[i] cancels downstream) ----
        #pragma unroll
        for (int mt = 0; mt < 4; mt++) {
            #pragma unroll
            for (int half = 0; half < 2; half++) {
                int li    = wm * 64 + mt * 16 + (lane >> 2) + half * 8;
                int mylbl = sLblI[li];
                float mp = -CUDART_INF_F, mn = CUDART_INF_F;
                #pragma unroll
                for (int nt = 0; nt < 4; nt++) {
                    int jl = wn * 32 + nt * 8 + (lane & 3) * 2;
                    float v0 = fmaf(-2.f, acc[mt][nt][half * 2],     sSqJ[jl]);
                    float v1 = fmaf(-2.f, acc[mt][nt][half * 2 + 1], sSqJ[jl + 1]);
                    if (sLblJ[jl]     == mylbl) mp = fmaxf(mp, v0); else mn = fminf(mn, v0);
                    if (sLblJ[jl + 1] == mylbl) mp = fmaxf(mp, v1); else mn = fminf(mn, v1);
                }
                #pragma unroll
                for (int o = 1; o <= 2; o <<= 1) {
                    mp = fmaxf(mp, __shfl_xor_sync(0xffffffffu, mp, o));
                    mn = fminf(mn, __shfl_xor_sync(0xffffffffu, mn, o));
                }
                if ((lane & 3) == 0) {
                    atomicMax(&g_maxenc[i0 + li], enc_f(mp));
                    atomicMin(&g_minenc[i0 + li], enc_f(mn));
                }
            }
        }
        // ---- col-side mining (off-diag only): val = sq[i] - 2*dot ----
        if (!diag) {
            #pragma unroll
            for (int nt = 0; nt < 4; nt++) {
                #pragma unroll
                for (int e = 0; e < 2; e++) {
                    int lj    = wn * 32 + nt * 8 + (lane & 3) * 2 + e;
                    int jlbl  = sLblJ[lj];
                    float mp = -CUDART_INF_F, mn = CUDART_INF_F;
                    #pragma unroll
                    for (int mt = 0; mt < 4; mt++) {
                        #pragma unroll
                        for (int half = 0; half < 2; half++) {
                            int li = wm * 64 + mt * 16 + (lane >> 2) + half * 8;
                            float v = fmaf(-2.f, acc[mt][nt][half * 2 + e], sSqI[li]);
                            if (sLblI[li] == jlbl) mp = fmaxf(mp, v);
                            else                   mn = fminf(mn, v);
                        }
                    }
                    #pragma unroll
                    for (int o = 4; o <= 16; o <<= 1) {
                        mp = fmaxf(mp, __shfl_xor_sync(0xffffffffu, mp, o));
                        mn = fminf(mn, __shfl_xor_sync(0xffffffffu, mn, o));
                    }
                    if (lane < 4) {
                        atomicMax(&g_maxenc[j0 + lj], enc_f(mp));
                        atomicMin(&g_minenc[j0 + lj], enc_f(mn));
                    }
                }
            }
        }

        bi = nbi; bj = nbj;
    }
}

// ---------- 2) final: decode, loss & precision (shuffle tree) ----------
__global__ void triplet_final(float* __restrict__ out) {
    __shared__ float wl[32], wp[32];
    int tid = threadIdx.x, lane = tid & 31, wid = tid >> 5;
    float lsum = 0.f, pcnt = 0.f;
    for (int i = tid; i < BB; i += 1024) {
        float mp = dec_f(g_maxenc[i]);
        float mn = dec_f(g_minenc[i]);
        float d = mp - mn + MARGIN_F;        // == dist_ap - dist_an + margin
        lsum += (d > 0.f) ? d : 0.f;
        pcnt += (mn > mp) ? 1.f : 0.f;
    }
    #pragma unroll
    for (int o = 16; o; o >>= 1) {
        lsum += __shfl_down_sync(0xffffffffu, lsum, o);
        pcnt += __shfl_down_sync(0xffffffffu, pcnt, o);
    }
    if (lane == 0) { wl[wid] = lsum; wp[wid] = pcnt; }
    __syncthreads();
    if (wid == 0) {
        float l = wl[lane], p = wp[lane];
        #pragma unroll
        for (int o = 16; o; o >>= 1) {
            l += __shfl_down_sync(0xffffffffu, l, o);
            p += __shfl_down_sync(0xffffffffu, p, o);
        }
        if (lane == 0) {
            out[0] = l / (float)BB;
            out[1] = p / (float)BB;
        }
    }
}

extern "C" void kernel_launch(void* const* d_in, const int* in_sizes, int n_in,
                              void* d_out, int out_size) {
    const float* x = (const float*)d_in[0];
    const int*   t = (const int*)d_in[1];   // JAX x64-disabled: int32
    float*       o = (float*)d_out;

    cudaFuncSetAttribute(triplet_mma, cudaFuncAttributeMaxDynamicSharedMemorySize, SMEM_DYN);

    prep_kernel<<<BB / 8, 256>>>(x);
    triplet_mma<<<GRID, 256, SMEM_DYN>>>(t);
    triplet_final<<<1, 1024>>>(o);
}

// round 14
// speedup vs baseline: 1.3216x; 1.0029x over previous
#include <cuda_runtime.h>
#include <cuda_fp16.h>
#include <cstdint>
#include <math_constants.h>

#define BB 8192
#define DD 256
#define TI 128
#define TJ 128
#define KC 64              // fp16 k-chunk = 128B rows
#define NCH (DD / KC)      // 4
#define NB  (BB / TI)      // 64
#define NTILES (NB * (NB + 1) / 2)   // 2080
#define GRID 296           // persistent: 148 SMs x 2 CTAs
#define MARGIN_F 0.3f
#define FINB 32            // final-reduce blocks
#define FIX_SCALE 1048576.0   // 2^20 fixed-point for deterministic merge

// dynamic smem layout: 2-stage
#define OFF_SQJ    0
#define OFF_LBLJ   512
#define OFF_SQI    1024
#define OFF_LBLI   1536
#define OFF_STAGE  2048
#define STAGE_BYTES 32768          // A tile 16KB + B tile 16KB
#define OFF_B      16384
#define SMEM_DYN   (OFF_STAGE + 2 * STAGE_BYTES)

__device__ __half g_xh[BB * DD];
__device__ float g_sq[BB];
__device__ unsigned int g_maxenc[BB];
__device__ unsigned int g_minenc[BB];
__device__ unsigned long long g_lacc;
__device__ unsigned int g_pacc;
__device__ unsigned int g_fdone;

__device__ __forceinline__ uint32_t smem_u32(const void* p) {
    uint32_t a;
    asm("{ .reg .u64 t; cvta.to.shared.u64 t, %1; cvt.u32.u64 %0, t; }" : "=r"(a) : "l"(p));
    return a;
}
__device__ __forceinline__ unsigned enc_f(float f) {
    unsigned u = __float_as_uint(f);
    return (u & 0x80000000u) ? ~u : (u | 0x80000000u);
}
__device__ __forceinline__ float dec_f(unsigned u) {
    return (u & 0x80000000u) ? __uint_as_float(u & 0x7FFFFFFFu) : __uint_as_float(~u);
}
#define CP_ASYNC(dst, src) \
    asm volatile("cp.async.cg.shared.global [%0], [%1], 16;" :: "r"(dst), "l"(src) : "memory")
#define CP_COMMIT() asm volatile("cp.async.commit_group;" ::: "memory")
#define CP_WAIT(n)  asm volatile("cp.async.wait_group " #n ";" ::: "memory")
#define LDSM4(r0,r1,r2,r3,a) \
    asm volatile("ldmatrix.sync.aligned.m8n8.x4.shared.b16 {%0,%1,%2,%3}, [%4];" \
                 : "=r"(r0),"=r"(r1),"=r"(r2),"=r"(r3) : "r"(a))
#define MMAH(d,a,b0,b1) \
    asm volatile("mma.sync.aligned.m16n8k16.row.col.f32.f16.f16.f32 " \
                 "{%0,%1,%2,%3}, {%4,%5,%6,%7}, {%8,%9}, {%0,%1,%2,%3};" \
                 : "+f"(d[0]),"+f"(d[1]),"+f"(d[2]),"+f"(d[3]) \
                 : "r"(a[0]),"r"(a[1]),"r"(a[2]),"r"(a[3]),"r"(b0),"r"(b1))

// ---------- 0) fp32 -> fp16 + row norms + init (2 rows/warp, MLP=4) ----------
__global__ void prep_kernel(const float* __restrict__ x) {
    int lane = threadIdx.x & 31, wrp = threadIdx.x >> 5;
    int r0 = blockIdx.x * 16 + wrp * 2;            // warp handles rows r0, r0+1
    const float4* s0 = (const float4*)(x + (size_t)r0 * DD);
    const float4* s1 = (const float4*)(x + (size_t)(r0 + 1) * DD);
    // all 4 loads in flight before any dependent work
    float4 v0 = s0[lane], v1 = s0[lane + 32];
    float4 v2 = s1[lane], v3 = s1[lane + 32];
    __half2* d0 = (__half2*)(g_xh + (size_t)r0 * DD);
    __half2* d1 = (__half2*)(g_xh + (size_t)(r0 + 1) * DD);
    d0[lane*2]          = __floats2half2_rn(v0.x, v0.y);
    d0[lane*2 + 1]      = __floats2half2_rn(v0.z, v0.w);
    d0[(lane+32)*2]     = __floats2half2_rn(v1.x, v1.y);
    d0[(lane+32)*2 + 1] = __floats2half2_rn(v1.z, v1.w);
    d1[lane*2]          = __floats2half2_rn(v2.x, v2.y);
    d1[lane*2 + 1]      = __floats2half2_rn(v2.z, v2.w);
    d1[(lane+32)*2]     = __floats2half2_rn(v3.x, v3.y);
    d1[(lane+32)*2 + 1] = __floats2half2_rn(v3.z, v3.w);

    float sa = fmaf(v0.x, v0.x, fmaf(v0.y, v0.y, fmaf(v0.z, v0.z, v0.w * v0.w)))
             + fmaf(v1.x, v1.x, fmaf(v1.y, v1.y, fmaf(v1.z, v1.z, v1.w * v1.w)));
    float sb = fmaf(v2.x, v2.x, fmaf(v2.y, v2.y, fmaf(v2.z, v2.z, v2.w * v2.w)))
             + fmaf(v3.x, v3.x, fmaf(v3.y, v3.y, fmaf(v3.z, v3.z, v3.w * v3.w)));
    #pragma unroll
    for (int o = 16; o; o >>= 1) {
        sa += __shfl_down_sync(0xffffffffu, sa, o);
        sb += __shfl_down_sync(0xffffffffu, sb, o);
    }
    if (lane == 0) {
        g_sq[r0] = sa;          g_sq[r0 + 1] = sb;
        g_maxenc[r0] = 0u;      g_maxenc[r0 + 1] = 0u;
        g_minenc[r0] = ~0u;     g_minenc[r0 + 1] = ~0u;
    }
    if (blockIdx.x == 0 && threadIdx.x == 0) {
        g_lacc = 0ull; g_pacc = 0u; g_fdone = 0u;
    }
}

// decode upper-triangle tile index -> (bi, bj)
__device__ __forceinline__ void tile2ij(int tile, int& bi, int& bj) {
    int rem = tile; bi = 0;
    while (rem >= NB - bi) { rem -= NB - bi; bi++; }
    bj = bi + rem;
}

// ---------- 1) fp16 Gram tiles (upper triangle, persistent, prefetch-overlap) ----------
// Tiles: 128 rows x 128B (8 chunks), swizzle ch ^ (row & 7) -> conflict-free ldmatrix.
__global__ void __launch_bounds__(256, 2)
triplet_mma(const int* __restrict__ tgt) {
    extern __shared__ char smem[];
    const uint32_t sb = smem_u32(smem);
    const int tid = threadIdx.x, lane = tid & 31, wid = tid >> 5;
    const int wm = wid >> 2, wn = wid & 3;          // warp tile: rows wm*64, cols wn*32

    auto issue_loads = [&](int i0, int j0, int c, int st) {
        const uint32_t abase = sb + OFF_STAGE + st * STAGE_BYTES;
        const uint32_t bbase = abase + OFF_B;
        const int kb = c * KC;
        #pragma unroll
        for (int t = 0; t < 4; t++) {
            int idx = t * 256 + tid;           // 0..1023
            int row = idx >> 3;                // 0..127
            int ch  = idx & 7;
            uint32_t d = (uint32_t)((ch ^ (row & 7)) * 16);
            const __half* sA = g_xh + (size_t)(i0 + row) * DD + kb + ch * 8;
            const __half* sB = g_xh + (size_t)(j0 + row) * DD + kb + ch * 8;
            CP_ASYNC(abase + row * 128 + d, sA);
            CP_ASYNC(bbase + row * 128 + d, sB);
        }
        CP_COMMIT();
    };

    auto compute_chunk = [&](uint32_t abase, uint32_t bbase, float (*acc)[4][4]) {
        #pragma unroll
        for (int ks = 0; ks < 4; ks++) {      // 4 k16 steps per 64-chunk
            uint32_t bh[8];
            #pragma unroll
            for (int p = 0; p < 2; p++) {
                int nrow = wn * 32 + p * 16 + (lane & 7) + ((lane >> 4) << 3);
                int ch   = ks * 2 + ((lane >> 3) & 1);
                uint32_t a_ = bbase + nrow * 128 + (uint32_t)((ch ^ (nrow & 7)) * 16);
                LDSM4(bh[p*4+0], bh[p*4+1], bh[p*4+2], bh[p*4+3], a_);
            }
            #pragma unroll
            for (int mt = 0; mt < 4; mt++) {
                int arow = wm * 64 + mt * 16 + (lane & 15);
                int ch   = ks * 2 + (lane >> 4);
                uint32_t a_ = abase + arow * 128 + (uint32_t)((ch ^ (arow & 7)) * 16);
                uint32_t ar[4];
                LDSM4(ar[0], ar[1], ar[2], ar[3], a_);
                #pragma unroll
                for (int nt = 0; nt < 4; nt++) {
                    uint32_t b0 = bh[(nt >> 1) * 4 + (nt & 1) * 2];
                    uint32_t b1 = bh[(nt >> 1) * 4 + (nt & 1) * 2 + 1];
                    MMAH(acc[mt][nt], ar, b0, b1);
                }
            }
        }
    };

    int bi, bj;
    tile2ij(blockIdx.x, bi, bj);
    if (blockIdx.x < NTILES) issue_loads(bi * TI, bj * TJ, 0, 0);   // prologue prefetch

    for (int tile = blockIdx.x; tile < NTILES; tile += GRID) {
        const int i0 = bi * TI, j0 = bj * TJ;
        const bool diag = (bi == bj);
        int nbi = 0, nbj = 0;
        const bool has_next = (tile + GRID < NTILES);
        if (has_next) tile2ij(tile + GRID, nbi, nbj);

        __syncthreads();   // prev epilogue done before sq/lbl smem rewrite
        if (tid < TJ) {
            ((float*)(smem + OFF_SQJ))[tid] = g_sq[j0 + tid];
            ((int*)(smem + OFF_LBLJ))[tid]  = tgt[j0 + tid];
        } else {
            int r = tid - TJ;
            ((float*)(smem + OFF_SQI))[r] = g_sq[i0 + r];
            ((int*)(smem + OFF_LBLI))[r]  = tgt[i0 + r];
        }

        float acc[4][4][4];
        #pragma unroll
        for (int mt = 0; mt < 4; mt++)
            #pragma unroll
            for (int nt = 0; nt < 4; nt++)
                #pragma unroll
                for (int e = 0; e < 4; e++) acc[mt][nt][e] = 0.f;

        // fully-unrolled chunk sequence: static stages, static branches
        // c = 0
        issue_loads(i0, j0, 1, 1); CP_WAIT(1); __syncthreads();
        compute_chunk(sb + OFF_STAGE, sb + OFF_STAGE + OFF_B, acc);
        __syncthreads();
        // c = 1
        issue_loads(i0, j0, 2, 0); CP_WAIT(1); __syncthreads();
        compute_chunk(sb + OFF_STAGE + STAGE_BYTES, sb + OFF_STAGE + STAGE_BYTES + OFF_B, acc);
        __syncthreads();
        // c = 2
        issue_loads(i0, j0, 3, 1); CP_WAIT(1); __syncthreads();
        compute_chunk(sb + OFF_STAGE, sb + OFF_STAGE + OFF_B, acc);
        __syncthreads();
        // c = 3
        if (has_next) { issue_loads(nbi * TI, nbj * TJ, 0, 0); CP_WAIT(1); }
        else          { CP_WAIT(0); }
        __syncthreads();
        compute_chunk(sb + OFF_STAGE + STAGE_BYTES, sb + OFF_STAGE + STAGE_BYTES + OFF_B, acc);

        const float* sSqJ  = (const float*)(smem + OFF_SQJ);
        const int*   sLblJ = (const int*)(smem + OFF_LBLJ);
        const float* sSqI  = (const float*)(smem + OFF_SQI);
        const int*   sLblI = (const int*)(smem + OFF_LBLI);

        // ---- row-side mining: val = sq[j] - 2*dot (sq[i] cancels downstream) ----
        #pragma unroll
        for (int mt = 0; mt < 4; mt++) {
            #pragma unroll
            for (int half = 0; half < 2; half++) {
                int li    = wm * 64 + mt * 16 + (lane >> 2) + half * 8;
                int mylbl = sLblI[li];
                float mp = -CUDART_INF_F, mn = CUDART_INF_F;
                #pragma unroll
                for (int nt = 0; nt < 4; nt++) {
                    int jl = wn * 32 + nt * 8 + (lane & 3) * 2;
                    float v0 = fmaf(-2.f, acc[mt][nt][half * 2],     sSqJ[jl]);
                    float v1 = fmaf(-2.f, acc[mt][nt][half * 2 + 1], sSqJ[jl + 1]);
                    if (sLblJ[jl]     == mylbl) mp = fmaxf(mp, v0); else mn = fminf(mn, v0);
                    if (sLblJ[jl + 1] == mylbl) mp = fmaxf(mp, v1); else mn = fminf(mn, v1);
                }
                #pragma unroll
                for (int o = 1; o <= 2; o <<= 1) {
                    mp = fmaxf(mp, __shfl_xor_sync(0xffffffffu, mp, o));
                    mn = fminf(mn, __shfl_xor_sync(0xffffffffu, mn, o));
                }
                if ((lane & 3) == 0) {
                    atomicMax(&g_maxenc[i0 + li], enc_f(mp));
                    atomicMin(&g_minenc[i0 + li], enc_f(mn));
                }
            }
        }
        // ---- col-side mining (off-diag only): val = sq[i] - 2*dot ----
        if (!diag) {
            #pragma unroll
            for (int nt = 0; nt < 4; nt++) {
                #pragma unroll
                for (int e = 0; e < 2; e++) {
                    int lj    = wn * 32 + nt * 8 + (lane & 3) * 2 + e;
                    int jlbl  = sLblJ[lj];
                    float mp = -CUDART_INF_F, mn = CUDART_INF_F;
                    #pragma unroll
                    for (int mt = 0; mt < 4; mt++) {
                        #pragma unroll
                        for (int half = 0; half < 2; half++) {
                            int li = wm * 64 + mt * 16 + (lane >> 2) + half * 8;
                            float v = fmaf(-2.f, acc[mt][nt][half * 2 + e], sSqI[li]);
                            if (sLblI[li] == jlbl) mp = fmaxf(mp, v);
                            else                   mn = fminf(mn, v);
                        }
                    }
                    #pragma unroll
                    for (int o = 4; o <= 16; o <<= 1) {
                        mp = fmaxf(mp, __shfl_xor_sync(0xffffffffu, mp, o));
                        mn = fminf(mn, __shfl_xor_sync(0xffffffffu, mn, o));
                    }
                    if (lane < 4) {
                        atomicMax(&g_maxenc[j0 + lj], enc_f(mp));
                        atomicMin(&g_minenc[j0 + lj], enc_f(mn));
                    }
                }
            }
        }

        bi = nbi; bj = nbj;
    }
}

// ---------- 2) final: 32 blocks, deterministic fixed-point merge ----------
__global__ void triplet_final(float* __restrict__ out) {
    __shared__ float wl[8];
    __shared__ unsigned int wp[8];
    __shared__ int s_last;
    int tid = threadIdx.x, lane = tid & 31, wid = tid >> 5;
    int i = blockIdx.x * 256 + tid;                 // exactly one element per thread
    float mp = dec_f(g_maxenc[i]);
    float mn = dec_f(g_minenc[i]);
    float dd = mp - mn + MARGIN_F;                  // == dist_ap - dist_an + margin
    float l = (dd > 0.f) ? dd : 0.f;
    unsigned int p = (mn > mp) ? 1u : 0u;
    #pragma unroll
    for (int o = 16; o; o >>= 1) {
        l += __shfl_down_sync(0xffffffffu, l, o);
        p += __shfl_down_sync(0xffffffffu, p, o);
    }
    if (lane == 0) { wl[wid] = l; wp[wid] = p; }
    __syncthreads();
    if (tid == 0) {
        float lb = 0.f; unsigned int pb = 0u;
        #pragma unroll
        for (int w = 0; w < 8; w++) { lb += wl[w]; pb += wp[w]; }
        // deterministic: integer adds commute exactly
        atomicAdd(&g_lacc, (unsigned long long)__double2ll_rn((double)lb * FIX_SCALE));
        atomicAdd(&g_pacc, pb);
        __threadfence();
        unsigned int old = atomicAdd(&g_fdone, 1u);
        s_last = (old == FINB - 1) ? 1 : 0;
    }
    __syncthreads();
    if (s_last && tid == 0) {
        __threadfence();
        out[0] = (float)((double)g_lacc / (FIX_SCALE * (double)BB));
        out[1] = (float)g_pacc / (float)BB;
    }
}

extern "C" void kernel_launch(void* const* d_in, const int* in_sizes, int n_in,
                              void* d_out, int out_size) {
    const float* x = (const float*)d_in[0];
    const int*   t = (const int*)d_in[1];   // JAX x64-disabled: int32
    float*       o = (float*)d_out;

    cudaFuncSetAttribute(triplet_mma, cudaFuncAttributeMaxDynamicSharedMemorySize, SMEM_DYN);

    prep_kernel<<<BB / 16, 256>>>(x);
    triplet_mma<<<GRID, 256, SMEM_DYN>>>(t);
    triplet_final<<<FINB, 256>>>(o);
}

// round 15
// speedup vs baseline: 1.3311x; 1.0072x over previous
#include <cuda_runtime.h>
#include <cuda_fp16.h>
#include <cstdint>
#include <math_constants.h>

#define BB 8192
#define DD 256
#define TI 128
#define TJ 128
#define KC 64              // fp16 k-chunk = 128B rows
#define NCH (DD / KC)      // 4
#define NB  (BB / TI)      // 64
#define NTILES (NB * (NB + 1) / 2)   // 2080
#define GRID 296           // persistent: 148 SMs x 2 CTAs
#define MARGIN_F 0.3f
#define FINB 32            // final-reduce blocks
#define FIX_SCALE 1048576.0   // 2^20 fixed-point for deterministic merge

// dynamic smem layout: 2-stage
#define OFF_SQJ    0
#define OFF_LBLJ   512
#define OFF_SQI    1024
#define OFF_LBLI   1536
#define OFF_STAGE  2048
#define STAGE_BYTES 32768          // A tile 16KB + B tile 16KB
#define OFF_B      16384
#define SMEM_DYN   (OFF_STAGE + 2 * STAGE_BYTES)

__device__ __half g_xh[BB * DD];
__device__ float g_sq[BB];
__device__ unsigned int g_maxenc[BB];
__device__ unsigned int g_minenc[BB];
__device__ unsigned long long g_lacc;
__device__ unsigned int g_pacc;
__device__ unsigned int g_fdone;

__device__ __forceinline__ uint32_t smem_u32(const void* p) {
    uint32_t a;
    asm("{ .reg .u64 t; cvta.to.shared.u64 t, %1; cvt.u32.u64 %0, t; }" : "=r"(a) : "l"(p));
    return a;
}
__device__ __forceinline__ unsigned enc_f(float f) {
    unsigned u = __float_as_uint(f);
    return (u & 0x80000000u) ? ~u : (u | 0x80000000u);
}
__device__ __forceinline__ float dec_f(unsigned u) {
    return (u & 0x80000000u) ? __uint_as_float(u & 0x7FFFFFFFu) : __uint_as_float(~u);
}
#define CP_ASYNC(dst, src) \
    asm volatile("cp.async.cg.shared.global [%0], [%1], 16;" :: "r"(dst), "l"(src) : "memory")
#define CP_COMMIT() asm volatile("cp.async.commit_group;" ::: "memory")
#define CP_WAIT(n)  asm volatile("cp.async.wait_group " #n ";" ::: "memory")
#define LDSM4(r0,r1,r2,r3,a) \
    asm volatile("ldmatrix.sync.aligned.m8n8.x4.shared.b16 {%0,%1,%2,%3}, [%4];" \
                 : "=r"(r0),"=r"(r1),"=r"(r2),"=r"(r3) : "r"(a))
#define MMAH(d,a,b0,b1) \
    asm volatile("mma.sync.aligned.m16n8k16.row.col.f32.f16.f16.f32 " \
                 "{%0,%1,%2,%3}, {%4,%5,%6,%7}, {%8,%9}, {%0,%1,%2,%3};" \
                 : "+f"(d[0]),"+f"(d[1]),"+f"(d[2]),"+f"(d[3]) \
                 : "r"(a[0]),"r"(a[1]),"r"(a[2]),"r"(a[3]),"r"(b0),"r"(b1))

// ---------- 0) fp32 -> fp16 + row norms + init (warp-per-row) ----------
__global__ void prep_kernel(const float* __restrict__ x) {
    int lane = threadIdx.x & 31, wrp = threadIdx.x >> 5;
    int row  = blockIdx.x * 8 + wrp;
    const float4* src = (const float4*)(x + (size_t)row * DD);
    __half2* dst = (__half2*)(g_xh + (size_t)row * DD);
    float s = 0.f;
    #pragma unroll
    for (int h = 0; h < 2; h++) {
        int idx = lane + h * 32;                     // 0..63 within row
        float4 v = src[idx];
        dst[idx * 2]     = __floats2half2_rn(v.x, v.y);
        dst[idx * 2 + 1] = __floats2half2_rn(v.z, v.w);
        s = fmaf(v.x, v.x, fmaf(v.y, v.y, fmaf(v.z, v.z, fmaf(v.w, v.w, s))));
    }
    #pragma unroll
    for (int o = 16; o; o >>= 1) s += __shfl_down_sync(0xffffffffu, s, o);
    if (lane == 0) {
        g_sq[row] = s;
        g_maxenc[row] = 0u;
        g_minenc[row] = ~0u;
    }
    if (blockIdx.x == 0 && threadIdx.x == 0) {
        g_lacc = 0ull; g_pacc = 0u; g_fdone = 0u;
    }
}

// decode upper-triangle tile index -> (bi, bj)
__device__ __forceinline__ void tile2ij(int tile, int& bi, int& bj) {
    int rem = tile; bi = 0;
    while (rem >= NB - bi) { rem -= NB - bi; bi++; }
    bj = bi + rem;
}

// ---------- 1) fp16 Gram tiles: 1 sync/chunk pipeline ----------
// Tiles: 128 rows x 128B (8 chunks), swizzle ch ^ (row & 7) -> conflict-free ldmatrix.
__global__ void __launch_bounds__(256, 2)
triplet_mma(const int* __restrict__ tgt) {
    extern __shared__ char smem[];
    const uint32_t sb = smem_u32(smem);
    const int tid = threadIdx.x, lane = tid & 31, wid = tid >> 5;
    const int wm = wid >> 2, wn = wid & 3;          // warp tile: rows wm*64, cols wn*32

    auto issue_loads = [&](int i0, int j0, int c, int st) {
        const uint32_t abase = sb + OFF_STAGE + st * STAGE_BYTES;
        const uint32_t bbase = abase + OFF_B;
        const int kb = c * KC;
        #pragma unroll
        for (int t = 0; t < 4; t++) {
            int idx = t * 256 + tid;           // 0..1023
            int row = idx >> 3;                // 0..127
            int ch  = idx & 7;
            uint32_t d = (uint32_t)((ch ^ (row & 7)) * 16);
            const __half* sA = g_xh + (size_t)(i0 + row) * DD + kb + ch * 8;
            const __half* sB = g_xh + (size_t)(j0 + row) * DD + kb + ch * 8;
            CP_ASYNC(abase + row * 128 + d, sA);
            CP_ASYNC(bbase + row * 128 + d, sB);
        }
        CP_COMMIT();
    };

    auto compute_chunk = [&](uint32_t abase, uint32_t bbase, float (*acc)[4][4]) {
        #pragma unroll
        for (int ks = 0; ks < 4; ks++) {      // 4 k16 steps per 64-chunk
            uint32_t bh[8];
            #pragma unroll
            for (int p = 0; p < 2; p++) {
                int nrow = wn * 32 + p * 16 + (lane & 7) + ((lane >> 4) << 3);
                int ch   = ks * 2 + ((lane >> 3) & 1);
                uint32_t a_ = bbase + nrow * 128 + (uint32_t)((ch ^ (nrow & 7)) * 16);
                LDSM4(bh[p*4+0], bh[p*4+1], bh[p*4+2], bh[p*4+3], a_);
            }
            #pragma unroll
            for (int mt = 0; mt < 4; mt++) {
                int arow = wm * 64 + mt * 16 + (lane & 15);
                int ch   = ks * 2 + (lane >> 4);
                uint32_t a_ = abase + arow * 128 + (uint32_t)((ch ^ (arow & 7)) * 16);
                uint32_t ar[4];
                LDSM4(ar[0], ar[1], ar[2], ar[3], a_);
                #pragma unroll
                for (int nt = 0; nt < 4; nt++) {
                    uint32_t b0 = bh[(nt >> 1) * 4 + (nt & 1) * 2];
                    uint32_t b1 = bh[(nt >> 1) * 4 + (nt & 1) * 2 + 1];
                    MMAH(acc[mt][nt], ar, b0, b1);
                }
            }
        }
    };

    const uint32_t st0a = sb + OFF_STAGE;
    const uint32_t st0b = st0a + OFF_B;
    const uint32_t st1a = sb + OFF_STAGE + STAGE_BYTES;
    const uint32_t st1b = st1a + OFF_B;

    int bi, bj;
    tile2ij(blockIdx.x, bi, bj);
    if (blockIdx.x < NTILES) issue_loads(bi * TI, bj * TJ, 0, 0);   // prologue: chunk0 -> stage0

    for (int tile = blockIdx.x; tile < NTILES; tile += GRID) {
        const int i0 = bi * TI, j0 = bj * TJ;
        const bool diag = (bi == bj);
        int nbi = 0, nbj = 0;
        const bool has_next = (tile + GRID < NTILES);
        if (has_next) tile2ij(tile + GRID, nbi, nbj);

        float acc[4][4][4];
        #pragma unroll
        for (int mt = 0; mt < 4; mt++)
            #pragma unroll
            for (int nt = 0; nt < 4; nt++)
                #pragma unroll
                for (int e = 0; e < 4; e++) acc[mt][nt][e] = 0.f;

        // One sync per chunk: WAIT -> sync (all warps past prev compute/epilogue)
        //                     -> issue next into the stage just vacated -> compute.
        // c = 0 (stage 0)
        CP_WAIT(0); __syncthreads();
        if (tid < TJ) {
            ((float*)(smem + OFF_SQJ))[tid] = g_sq[j0 + tid];
            ((int*)(smem + OFF_LBLJ))[tid]  = tgt[j0 + tid];
        } else {
            int r = tid - TJ;
            ((float*)(smem + OFF_SQI))[r] = g_sq[i0 + r];
            ((int*)(smem + OFF_LBLI))[r]  = tgt[i0 + r];
        }
        issue_loads(i0, j0, 1, 1);
        compute_chunk(st0a, st0b, acc);
        // c = 1 (stage 1)
        CP_WAIT(0); __syncthreads();
        issue_loads(i0, j0, 2, 0);
        compute_chunk(st1a, st1b, acc);
        // c = 2 (stage 0)
        CP_WAIT(0); __syncthreads();
        issue_loads(i0, j0, 3, 1);
        compute_chunk(st0a, st0b, acc);
        // c = 3 (stage 1); next tile's chunk0 loads during epilogue
        CP_WAIT(0); __syncthreads();
        if (has_next) issue_loads(nbi * TI, nbj * TJ, 0, 0);
        compute_chunk(st1a, st1b, acc);

        const float* sSqJ  = (const float*)(smem + OFF_SQJ);
        const int*   sLblJ = (const int*)(smem + OFF_LBLJ);
        const float* sSqI  = (const float*)(smem + OFF_SQI);
        const int*   sLblI = (const int*)(smem + OFF_LBLI);

        // ---- row-side mining: val = sq[j] - 2*dot (sq[i] cancels downstream) ----
        #pragma unroll
        for (int mt = 0; mt < 4; mt++) {
            #pragma unroll
            for (int half = 0; half < 2; half++) {
                int li    = wm * 64 + mt * 16 + (lane >> 2) + half * 8;
                int mylbl = sLblI[li];
                float mp = -CUDART_INF_F, mn = CUDART_INF_F;
                #pragma unroll
                for (int nt = 0; nt < 4; nt++) {
                    int jl = wn * 32 + nt * 8 + (lane & 3) * 2;
                    float v0 = fmaf(-2.f, acc[mt][nt][half * 2],     sSqJ[jl]);
                    float v1 = fmaf(-2.f, acc[mt][nt][half * 2 + 1], sSqJ[jl + 1]);
                    if (sLblJ[jl]     == mylbl) mp = fmaxf(mp, v0); else mn = fminf(mn, v0);
                    if (sLblJ[jl + 1] == mylbl) mp = fmaxf(mp, v1); else mn = fminf(mn, v1);
                }
                #pragma unroll
                for (int o = 1; o <= 2; o <<= 1) {
                    mp = fmaxf(mp, __shfl_xor_sync(0xffffffffu, mp, o));
                    mn = fminf(mn, __shfl_xor_sync(0xffffffffu, mn, o));
                }
                if ((lane & 3) == 0) {
                    atomicMax(&g_maxenc[i0 + li], enc_f(mp));
                    atomicMin(&g_minenc[i0 + li], enc_f(mn));
                }
            }
        }
        // ---- col-side mining (off-diag only): val = sq[i] - 2*dot ----
        if (!diag) {
            #pragma unroll
            for (int nt = 0; nt < 4; nt++) {
                #pragma unroll
                for (int e = 0; e < 2; e++) {
                    int lj    = wn * 32 + nt * 8 + (lane & 3) * 2 + e;
                    int jlbl  = sLblJ[lj];
                    float mp = -CUDART_INF_F, mn = CUDART_INF_F;
                    #pragma unroll
                    for (int mt = 0; mt < 4; mt++) {
                        #pragma unroll
                        for (int half = 0; half < 2; half++) {
                            int li = wm * 64 + mt * 16 + (lane >> 2) + half * 8;
                            float v = fmaf(-2.f, acc[mt][nt][half * 2 + e], sSqI[li]);
                            if (sLblI[li] == jlbl) mp = fmaxf(mp, v);
                            else                   mn = fminf(mn, v);
                        }
                    }
                    #pragma unroll
                    for (int o = 4; o <= 16; o <<= 1) {
                        mp = fmaxf(mp, __shfl_xor_sync(0xffffffffu, mp, o));
                        mn = fminf(mn, __shfl_xor_sync(0xffffffffu, mn, o));
                    }
                    if (lane < 4) {
                        atomicMax(&g_maxenc[j0 + lj], enc_f(mp));
                        atomicMin(&g_minenc[j0 + lj], enc_f(mn));
                    }
                }
            }
        }

        bi = nbi; bj = nbj;
    }
}

// ---------- 2) final: 32 blocks, deterministic fixed-point merge ----------
__global__ void triplet_final(float* __restrict__ out) {
    __shared__ float wl[8];
    __shared__ unsigned int wp[8];
    __shared__ int s_last;
    int tid = threadIdx.x, lane = tid & 31, wid = tid >> 5;
    int i = blockIdx.x * 256 + tid;                 // exactly one element per thread
    float mp = dec_f(g_maxenc[i]);
    float mn = dec_f(g_minenc[i]);
    float dd = mp - mn + MARGIN_F;                  // == dist_ap - dist_an + margin
    float l = (dd > 0.f) ? dd : 0.f;
    unsigned int p = (mn > mp) ? 1u : 0u;
    #pragma unroll
    for (int o = 16; o; o >>= 1) {
        l += __shfl_down_sync(0xffffffffu, l, o);
        p += __shfl_down_sync(0xffffffffu, p, o);
    }
    if (lane == 0) { wl[wid] = l; wp[wid] = p; }
    __syncthreads();
    if (tid == 0) {
        float lb = 0.f; unsigned int pb = 0u;
        #pragma unroll
        for (int w = 0; w < 8; w++) { lb += wl[w]; pb += wp[w]; }
        atomicAdd(&g_lacc, (unsigned long long)__double2ll_rn((double)lb * FIX_SCALE));
        atomicAdd(&g_pacc, pb);
        __threadfence();
        unsigned int old = atomicAdd(&g_fdone, 1u);
        s_last = (old == FINB - 1) ? 1 : 0;
    }
    __syncthreads();
    if (s_last && tid == 0) {
        __threadfence();
        out[0] = (float)((double)g_lacc / (FIX_SCALE * (double)BB));
        out[1] = (float)g_pacc / (float)BB;
    }
}

extern "C" void kernel_launch(void* const* d_in, const int* in_sizes, int n_in,
                              void* d_out, int out_size) {
    const float* x = (const float*)d_in[0];
    const int*   t = (const int*)d_in[1];   // JAX x64-disabled: int32
    float*       o = (float*)d_out;

    cudaFuncSetAttribute(triplet_mma, cudaFuncAttributeMaxDynamicSharedMemorySize, SMEM_DYN);

    prep_kernel<<<BB / 8, 256>>>(x);
    triplet_mma<<<GRID, 256, SMEM_DYN>>>(t);
    triplet_final<<<FINB, 256>>>(o);
}

// round 16
// speedup vs baseline: 1.3592x; 1.0211x over previous
#include <cuda_runtime.h>
#include <cuda_fp16.h>
#include <cstdint>
#include <math_constants.h>

#define BB 8192
#define DD 256
#define TI 128
#define TJ 128
#define KC 64              // fp16 k-chunk = 128B rows
#define NCH (DD / KC)      // 4
#define NB  (BB / TI)      // 64
#define NTILES (NB * (NB + 1) / 2)   // 2080
#define GRID 296           // persistent: 148 SMs x 2 CTAs
#define MARGIN_F 0.3f
#define FINB 32            // final-reduce blocks
#define FIX_SCALE 1048576.0   // 2^20 fixed-point for deterministic merge

// dynamic smem layout: 2-stage
#define OFF_SQJ    0
#define OFF_LBLJ   512
#define OFF_SQI    1024
#define OFF_LBLI   1536
#define OFF_STAGE  2048
#define STAGE_BYTES 32768          // A tile 16KB + B tile 16KB
#define OFF_B      16384
#define SMEM_DYN   (OFF_STAGE + 2 * STAGE_BYTES)

__device__ __half g_xh[BB * DD];
__device__ float g_sq[BB];
__device__ unsigned int g_maxenc[BB];
__device__ unsigned int g_minenc[BB];
__device__ unsigned long long g_lacc;
__device__ unsigned int g_pacc;
__device__ unsigned int g_fdone;

__device__ __forceinline__ uint32_t smem_u32(const void* p) {
    uint32_t a;
    asm("{ .reg .u64 t; cvta.to.shared.u64 t, %1; cvt.u32.u64 %0, t; }" : "=r"(a) : "l"(p));
    return a;
}
__device__ __forceinline__ unsigned enc_f(float f) {
    unsigned u = __float_as_uint(f);
    return (u & 0x80000000u) ? ~u : (u | 0x80000000u);
}
__device__ __forceinline__ float dec_f(unsigned u) {
    return (u & 0x80000000u) ? __uint_as_float(u & 0x7FFFFFFFu) : __uint_as_float(~u);
}
#define CP_ASYNC(dst, src) \
    asm volatile("cp.async.cg.shared.global [%0], [%1], 16;" :: "r"(dst), "l"(src) : "memory")
#define CP_COMMIT() asm volatile("cp.async.commit_group;" ::: "memory")
#define CP_WAIT(n)  asm volatile("cp.async.wait_group " #n ";" ::: "memory")
#define LDSM4(r0,r1,r2,r3,a) \
    asm volatile("ldmatrix.sync.aligned.m8n8.x4.shared.b16 {%0,%1,%2,%3}, [%4];" \
                 : "=r"(r0),"=r"(r1),"=r"(r2),"=r"(r3) : "r"(a))
#define MMAH(d,a,b0,b1) \
    asm volatile("mma.sync.aligned.m16n8k16.row.col.f32.f16.f16.f32 " \
                 "{%0,%1,%2,%3}, {%4,%5,%6,%7}, {%8,%9}, {%0,%1,%2,%3};" \
                 : "+f"(d[0]),"+f"(d[1]),"+f"(d[2]),"+f"(d[3]) \
                 : "r"(a[0]),"r"(a[1]),"r"(a[2]),"r"(a[3]),"r"(b0),"r"(b1))

// ---------- 0) fp32 -> fp16 + row norms + init (warp-per-row, loads hoisted) ----------
__global__ void prep_kernel(const float* __restrict__ x) {
    int lane = threadIdx.x & 31, wrp = threadIdx.x >> 5;
    int row  = blockIdx.x * 8 + wrp;
    const float4* src = (const float4*)(x + (size_t)row * DD);
    __half2* dst = (__half2*)(g_xh + (size_t)row * DD);
    // both loads in flight before any dependent work (MLP=2)
    float4 v0 = src[lane];
    float4 v1 = src[lane + 32];
    dst[lane * 2]            = __floats2half2_rn(v0.x, v0.y);
    dst[lane * 2 + 1]        = __floats2half2_rn(v0.z, v0.w);
    dst[(lane + 32) * 2]     = __floats2half2_rn(v1.x, v1.y);
    dst[(lane + 32) * 2 + 1] = __floats2half2_rn(v1.z, v1.w);
    float s = fmaf(v0.x, v0.x, fmaf(v0.y, v0.y, fmaf(v0.z, v0.z, v0.w * v0.w)))
            + fmaf(v1.x, v1.x, fmaf(v1.y, v1.y, fmaf(v1.z, v1.z, v1.w * v1.w)));
    #pragma unroll
    for (int o = 16; o; o >>= 1) s += __shfl_down_sync(0xffffffffu, s, o);
    if (lane == 0) {
        g_sq[row] = s;
        g_maxenc[row] = 0u;
        g_minenc[row] = ~0u;
    }
    if (blockIdx.x == 0 && threadIdx.x == 0) {
        g_lacc = 0ull; g_pacc = 0u; g_fdone = 0u;
    }
}

// decode upper-triangle tile index -> (bi, bj)
__device__ __forceinline__ void tile2ij(int tile, int& bi, int& bj) {
    int rem = tile; bi = 0;
    while (rem >= NB - bi) { rem -= NB - bi; bi++; }
    bj = bi + rem;
}

// ---------- 1) fp16 Gram tiles: 1 sync/chunk pipeline ----------
// Tiles: 128 rows x 128B (8 chunks), swizzle ch ^ (row & 7) -> conflict-free ldmatrix.
__global__ void __launch_bounds__(256, 2)
triplet_mma(const int* __restrict__ tgt) {
    extern __shared__ char smem[];
    const uint32_t sb = smem_u32(smem);
    const int tid = threadIdx.x, lane = tid & 31, wid = tid >> 5;
    const int wm = wid >> 2, wn = wid & 3;          // warp tile: rows wm*64, cols wn*32

    auto issue_loads = [&](int i0, int j0, int c, int st) {
        const uint32_t abase = sb + OFF_STAGE + st * STAGE_BYTES;
        const uint32_t bbase = abase + OFF_B;
        const int kb = c * KC;
        #pragma unroll
        for (int t = 0; t < 4; t++) {
            int idx = t * 256 + tid;           // 0..1023
            int row = idx >> 3;                // 0..127
            int ch  = idx & 7;
            uint32_t d = (uint32_t)((ch ^ (row & 7)) * 16);
            const __half* sA = g_xh + (size_t)(i0 + row) * DD + kb + ch * 8;
            const __half* sB = g_xh + (size_t)(j0 + row) * DD + kb + ch * 8;
            CP_ASYNC(abase + row * 128 + d, sA);
            CP_ASYNC(bbase + row * 128 + d, sB);
        }
        CP_COMMIT();
    };

    auto compute_chunk = [&](uint32_t abase, uint32_t bbase, float (*acc)[4][4]) {
        #pragma unroll
        for (int ks = 0; ks < 4; ks++) {      // 4 k16 steps per 64-chunk
            uint32_t bh[8];
            #pragma unroll
            for (int p = 0; p < 2; p++) {
                int nrow = wn * 32 + p * 16 + (lane & 7) + ((lane >> 4) << 3);
                int ch   = ks * 2 + ((lane >> 3) & 1);
                uint32_t a_ = bbase + nrow * 128 + (uint32_t)((ch ^ (nrow & 7)) * 16);
                LDSM4(bh[p*4+0], bh[p*4+1], bh[p*4+2], bh[p*4+3], a_);
            }
            #pragma unroll
            for (int mt = 0; mt < 4; mt++) {
                int arow = wm * 64 + mt * 16 + (lane & 15);
                int ch   = ks * 2 + (lane >> 4);
                uint32_t a_ = abase + arow * 128 + (uint32_t)((ch ^ (arow & 7)) * 16);
                uint32_t ar[4];
                LDSM4(ar[0], ar[1], ar[2], ar[3], a_);
                #pragma unroll
                for (int nt = 0; nt < 4; nt++) {
                    uint32_t b0 = bh[(nt >> 1) * 4 + (nt & 1) * 2];
                    uint32_t b1 = bh[(nt >> 1) * 4 + (nt & 1) * 2 + 1];
                    MMAH(acc[mt][nt], ar, b0, b1);
                }
            }
        }
    };

    const uint32_t st0a = sb + OFF_STAGE;
    const uint32_t st0b = st0a + OFF_B;
    const uint32_t st1a = sb + OFF_STAGE + STAGE_BYTES;
    const uint32_t st1b = st1a + OFF_B;

    int bi, bj;
    tile2ij(blockIdx.x, bi, bj);
    if (blockIdx.x < NTILES) issue_loads(bi * TI, bj * TJ, 0, 0);   // prologue: chunk0 -> stage0

    for (int tile = blockIdx.x; tile < NTILES; tile += GRID) {
        const int i0 = bi * TI, j0 = bj * TJ;
        const bool diag = (bi == bj);
        int nbi = 0, nbj = 0;
        const bool has_next = (tile + GRID < NTILES);
        if (has_next) tile2ij(tile + GRID, nbi, nbj);

        float acc[4][4][4];
        #pragma unroll
        for (int mt = 0; mt < 4; mt++)
            #pragma unroll
            for (int nt = 0; nt < 4; nt++)
                #pragma unroll
                for (int e = 0; e < 4; e++) acc[mt][nt][e] = 0.f;

        // One sync per chunk: WAIT -> sync -> issue next into vacated stage -> compute.
        // c = 0 (stage 0)
        CP_WAIT(0); __syncthreads();
        if (tid < TJ) {
            ((float*)(smem + OFF_SQJ))[tid] = g_sq[j0 + tid];
            ((int*)(smem + OFF_LBLJ))[tid]  = tgt[j0 + tid];
        } else {
            int r = tid - TJ;
            ((float*)(smem + OFF_SQI))[r] = g_sq[i0 + r];
            ((int*)(smem + OFF_LBLI))[r]  = tgt[i0 + r];
        }
        issue_loads(i0, j0, 1, 1);
        compute_chunk(st0a, st0b, acc);
        // c = 1 (stage 1)
        CP_WAIT(0); __syncthreads();
        issue_loads(i0, j0, 2, 0);
        compute_chunk(st1a, st1b, acc);
        // c = 2 (stage 0)
        CP_WAIT(0); __syncthreads();
        issue_loads(i0, j0, 3, 1);
        compute_chunk(st0a, st0b, acc);
        // c = 3 (stage 1); next tile's chunk0 loads during epilogue
        CP_WAIT(0); __syncthreads();
        if (has_next) issue_loads(nbi * TI, nbj * TJ, 0, 0);
        compute_chunk(st1a, st1b, acc);

        const float* sSqJ  = (const float*)(smem + OFF_SQJ);
        const int*   sLblJ = (const int*)(smem + OFF_LBLJ);
        const float* sSqI  = (const float*)(smem + OFF_SQI);
        const int*   sLblI = (const int*)(smem + OFF_LBLI);

        // ---- row-side mining: val = sq[j] - 2*dot (sq[i] cancels downstream) ----
        #pragma unroll
        for (int mt = 0; mt < 4; mt++) {
            #pragma unroll
            for (int half = 0; half < 2; half++) {
                int li    = wm * 64 + mt * 16 + (lane >> 2) + half * 8;
                int mylbl = sLblI[li];
                float mp = -CUDART_INF_F, mn = CUDART_INF_F;
                #pragma unroll
                for (int nt = 0; nt < 4; nt++) {
                    int jl = wn * 32 + nt * 8 + (lane & 3) * 2;
                    float v0 = fmaf(-2.f, acc[mt][nt][half * 2],     sSqJ[jl]);
                    float v1 = fmaf(-2.f, acc[mt][nt][half * 2 + 1], sSqJ[jl + 1]);
                    if (sLblJ[jl]     == mylbl) mp = fmaxf(mp, v0); else mn = fminf(mn, v0);
                    if (sLblJ[jl + 1] == mylbl) mp = fmaxf(mp, v1); else mn = fminf(mn, v1);
                }
                #pragma unroll
                for (int o = 1; o <= 2; o <<= 1) {
                    mp = fmaxf(mp, __shfl_xor_sync(0xffffffffu, mp, o));
                    mn = fminf(mn, __shfl_xor_sync(0xffffffffu, mn, o));
                }
                if ((lane & 3) == 0) {
                    atomicMax(&g_maxenc[i0 + li], enc_f(mp));
                    atomicMin(&g_minenc[i0 + li], enc_f(mn));
                }
            }
        }
        // ---- col-side mining (off-diag only): val = sq[i] - 2*dot ----
        if (!diag) {
            #pragma unroll
            for (int nt = 0; nt < 4; nt++) {
                #pragma unroll
                for (int e = 0; e < 2; e++) {
                    int lj    = wn * 32 + nt * 8 + (lane & 3) * 2 + e;
                    int jlbl  = sLblJ[lj];
                    float mp = -CUDART_INF_F, mn = CUDART_INF_F;
                    #pragma unroll
                    for (int mt = 0; mt < 4; mt++) {
                        #pragma unroll
                        for (int half = 0; half < 2; half++) {
                            int li = wm * 64 + mt * 16 + (lane >> 2) + half * 8;
                            float v = fmaf(-2.f, acc[mt][nt][half * 2 + e], sSqI[li]);
                            if (sLblI[li] == jlbl) mp = fmaxf(mp, v);
                            else                   mn = fminf(mn, v);
                        }
                    }
                    #pragma unroll
                    for (int o = 4; o <= 16; o <<= 1) {
                        mp = fmaxf(mp, __shfl_xor_sync(0xffffffffu, mp, o));
                        mn = fminf(mn, __shfl_xor_sync(0xffffffffu, mn, o));
                    }
                    if (lane < 4) {
                        atomicMax(&g_maxenc[j0 + lj], enc_f(mp));
                        atomicMin(&g_minenc[j0 + lj], enc_f(mn));
                    }
                }
            }
        }

        bi = nbi; bj = nbj;
    }
}

// ---------- 2) final: 32 blocks, deterministic fixed-point merge ----------
__global__ void triplet_final(float* __restrict__ out) {
    __shared__ float wl[8];
    __shared__ unsigned int wp[8];
    __shared__ int s_last;
    int tid = threadIdx.x, lane = tid & 31, wid = tid >> 5;
    int i = blockIdx.x * 256 + tid;                 // exactly one element per thread
    float mp = dec_f(g_maxenc[i]);
    float mn = dec_f(g_minenc[i]);
    float dd = mp - mn + MARGIN_F;                  // == dist_ap - dist_an + margin
    float l = (dd > 0.f) ? dd : 0.f;
    unsigned int p = (mn > mp) ? 1u : 0u;
    #pragma unroll
    for (int o = 16; o; o >>= 1) {
        l += __shfl_down_sync(0xffffffffu, l, o);
        p += __shfl_down_sync(0xffffffffu, p, o);
    }
    if (lane == 0) { wl[wid] = l; wp[wid] = p; }
    __syncthreads();
    if (tid == 0) {
        float lb = 0.f; unsigned int pb = 0u;
        #pragma unroll
        for (int w = 0; w < 8; w++) { lb += wl[w]; pb += wp[w]; }
        atomicAdd(&g_lacc, (unsigned long long)__double2ll_rn((double)lb * FIX_SCALE));
        atomicAdd(&g_pacc, pb);
        __threadfence();
        unsigned int old = atomicAdd(&g_fdone, 1u);
        s_last = (old == FINB - 1) ? 1 : 0;
    }
    __syncthreads();
    if (s_last && tid == 0) {
        __threadfence();
        out[0] = (float)((double)g_lacc / (FIX_SCALE * (double)BB));
        out[1] = (float)g_pacc / (float)BB;
    }
}

extern "C" void kernel_launch(void* const* d_in, const int* in_sizes, int n_in,
                              void* d_out, int out_size) {
    const float* x = (const float*)d_in[0];
    const int*   t = (const int*)d_in[1];   // JAX x64-disabled: int32
    float*       o = (float*)d_out;

    cudaFuncSetAttribute(triplet_mma, cudaFuncAttributeMaxDynamicSharedMemorySize, SMEM_DYN);

    prep_kernel<<<BB / 8, 256>>>(x);
    triplet_mma<<<GRID, 256, SMEM_DYN>>>(t);
    triplet_final<<<FINB, 256>>>(o);
}